// round 7
// baseline (speedup 1.0000x reference)
#include <cuda_runtime.h>
#include <cuda_bf16.h>
#include <cstdint>

#define BATCH 256
#define TOBS  80
#define TTOT  160
#define HID   2048
#define HID4  8192
#define BH    (BATCH * HID)

#define NT      128                  // 4 warps: wn in {0,1} x kh in {0,1}
#define BM      64
#define BN      128
#define BK      64                   // K per chunk (bf16) = 128 bytes/row
#define NCH     96                   // 3 * (2048/64) concatenated-K chunks
#define NSTAGE  4
#define TILE_A  (BM * 128)           // 8 KB
#define TILE_BB (BN * 128)           // 16 KB
#define STAGE_B (TILE_A + TILE_BB)   // 24 KB
#define CTRL_B  2048
#define SMEM_DYN (1024 + CTRL_B + NSTAGE * STAGE_B)
#define GSTRIDE 130                  // gates smem row stride (floats)

// ---------------- persistent device state ----------------
__device__ float          g_c[BH];
__device__ __nv_bfloat16  g_hhi[2 * BH];
__device__ __nv_bfloat16  g_hlo[2 * BH];
__device__ __nv_bfloat16  g_whi[(size_t)HID4 * HID];   // gate-interleaved W_hh hi
__device__ __nv_bfloat16  g_wlo[(size_t)HID4 * HID];   // gate-interleaved W_hh lo

// ---------------- helpers ----------------
static __device__ __forceinline__ uint32_t smem_u32(const void* p) {
    uint32_t a;
    asm("{ .reg .u64 t; cvta.to.shared.u64 t, %1; cvt.u32.u64 %0, t; }" : "=r"(a) : "l"(p));
    return a;
}
static __device__ __forceinline__ void cpa16(uint32_t dst, const void* src) {
    asm volatile("cp.async.cg.shared.global [%0], [%1], 16;" :: "r"(dst), "l"(src) : "memory");
}
static __device__ __forceinline__ void cpa_commit() {
    asm volatile("cp.async.commit_group;" ::: "memory");
}
template <int N>
static __device__ __forceinline__ void cpa_wait() {
    asm volatile("cp.async.wait_group %0;" :: "n"(N) : "memory");
}
static __device__ __forceinline__ void ldsm4(uint32_t* r, uint32_t a) {
    asm volatile("ldmatrix.sync.aligned.m8n8.x4.shared.b16 {%0,%1,%2,%3}, [%4];"
                 : "=r"(r[0]), "=r"(r[1]), "=r"(r[2]), "=r"(r[3]) : "r"(a));
}
static __device__ __forceinline__ void mma16816(float* d, const uint32_t* a, const uint32_t* b) {
    asm volatile("mma.sync.aligned.m16n8k16.row.col.f32.bf16.bf16.f32 "
                 "{%0,%1,%2,%3}, {%4,%5,%6,%7}, {%8,%9}, {%0,%1,%2,%3};"
                 : "+f"(d[0]), "+f"(d[1]), "+f"(d[2]), "+f"(d[3])
                 : "r"(a[0]), "r"(a[1]), "r"(a[2]), "r"(a[3]), "r"(b[0]), "r"(b[1]));
}
static __device__ __forceinline__ float sig_f(float x) {
    return __fdividef(1.0f, 1.0f + __expf(-x));
}
static __device__ __forceinline__ float tanh_f(float x) {
    return __fdividef(2.0f, 1.0f + __expf(-2.0f * x)) - 1.0f;
}

// Load one chunk (A tile BMxBK + B tile BNxBK) into a stage via cp.async, SW128.
static __device__ __forceinline__ void load_chunk(
    uint32_t st, const __nv_bfloat16* __restrict__ A, const __nv_bfloat16* __restrict__ B,
    int m0, int n0, int koff, int tid)
{
    // A: 64 rows * 8 16B-chunks = 512 units, 128 threads -> 4 iters
#pragma unroll
    for (int r = 0; r < 4; ++r) {
        int q   = tid + NT * r;
        int row = q >> 3;
        int cb  = (q & 7) * 16;
        uint32_t sw = (uint32_t)(row * 128) + (uint32_t)(cb ^ ((row & 7) * 16));
        const char* ga = (const char*)(A + (size_t)(m0 + row) * HID + koff) + cb;
        cpa16(st + sw, ga);
    }
    // B: 128 rows * 8 = 1024 units -> 8 iters
#pragma unroll
    for (int r = 0; r < 8; ++r) {
        int q   = tid + NT * r;
        int row = q >> 3;
        int cb  = (q & 7) * 16;
        uint32_t sw = (uint32_t)(row * 128) + (uint32_t)(cb ^ ((row & 7) * 16));
        const char* gb = (const char*)(B + (size_t)(n0 + row) * HID + koff) + cb;
        cpa16(st + TILE_A + sw, gb);
    }
}

// ---------------- prep kernels ----------------
__global__ void wconv_kernel(const float* __restrict__ W,
                             __nv_bfloat16* __restrict__ whi,
                             __nv_bfloat16* __restrict__ wlo)
{
    int n = blockIdx.x;                  // gate-interleaved row: n = 4*j + g
    int j = n >> 2, g = n & 3;
    const float4* src = (const float4*)(W + ((size_t)g * HID + j) * HID);
    size_t dst = (size_t)n * HID;
#pragma unroll
    for (int r = 0; r < 2; ++r) {
        int q = threadIdx.x + 256 * r;
        float4 v = src[q];
        int k = q * 4;
        float xs[4] = {v.x, v.y, v.z, v.w};
#pragma unroll
        for (int c = 0; c < 4; ++c) {
            __nv_bfloat16 hi = __float2bfloat16(xs[c]);
            whi[dst + k + c] = hi;
            wlo[dst + k + c] = __float2bfloat16(xs[c] - __bfloat162float(hi));
        }
    }
}

__global__ void init_kernel(float* __restrict__ cbuf,
                            __nv_bfloat16* __restrict__ h0hi,
                            __nv_bfloat16* __restrict__ h0lo,
                            float* __restrict__ out,
                            const float* __restrict__ b_lin)
{
    int i = blockIdx.x * blockDim.x + threadIdx.x;
    if (i < BH) {
        cbuf[i] = 0.0f;
        h0hi[i] = __float2bfloat16(0.0f);
        h0lo[i] = __float2bfloat16(0.0f);
    }
    if (i < BATCH * TTOT) out[i] = b_lin[0];
}

// ---------------- fused LSTM step ----------------
__global__ void __launch_bounds__(NT, 2)
lstm_step(const __nv_bfloat16* __restrict__ Ahi, const __nv_bfloat16* __restrict__ Alo,
          __nv_bfloat16* __restrict__ Ahi_n, __nv_bfloat16* __restrict__ Alo_n,
          float* __restrict__ cbuf,
          const __nv_bfloat16* __restrict__ Whi, const __nv_bfloat16* __restrict__ Wlo,
          const float* __restrict__ W_ih, const float* __restrict__ b_ih,
          const float* __restrict__ b_hh, const float* __restrict__ W_lin,
          float* __restrict__ out,
          const float* __restrict__ xvec, int xstride, int t)
{
    extern __shared__ char smem_raw[];
    const int tid  = threadIdx.x;
    const int wid  = tid >> 5;
    const int lane = tid & 31;
    const int wn   = wid & 1;            // n-half: cols wn*64..wn*64+63
    const int kh   = wid >> 1;           // k-half: k bytes kh*64..kh*64+63 of each 128B row
    const int m0 = blockIdx.x * BM;
    const int n0 = blockIdx.y * BN;      // gate-interleaved col base
    const int j0 = n0 >> 2;

    uint32_t sb    = smem_u32(smem_raw);
    uint32_t sbase = (sb + 1023) & ~1023u;
    char*    ctrl  = smem_raw + (sbase - sb);
    uint32_t tiles = sbase + CTRL_B;
    float* bias_s = (float*)(ctrl + 0);      // 128
    float* wih_s  = (float*)(ctrl + 512);    // 128
    float* rowsum = (float*)(ctrl + 1024);   // 64
    float* wlin_s = (float*)(ctrl + 1536);   // 32
    float* gbuf   = (float*)(smem_raw + (tiles - sb));  // gates merge buffer (reuses stage 0/1)

    {
        int j = j0 + (tid >> 2);
        int g = tid & 3;
        bias_s[tid] = b_ih[g * HID + j] + b_hh[g * HID + j];
        wih_s[tid]  = W_ih[g * HID + j];
    }
    if (tid < 64) rowsum[tid] = 0.0f;
    if (tid < 32) wlin_s[tid] = W_lin[j0 + tid];
    __syncthreads();

    float acc[4][8][4];
#pragma unroll
    for (int i = 0; i < 4; ++i)
#pragma unroll
        for (int jf = 0; jf < 8; ++jf)
#pragma unroll
            for (int kf = 0; kf < 4; ++kf) acc[i][jf][kf] = 0.0f;

    // ldmatrix addressing (SW128: xor (row&7)*16; row-invariant per lane)
    const int xm = (lane & 7) * 16;
    int arow[4], brow[4];
#pragma unroll
    for (int mf = 0; mf < 4; ++mf)
        arow[mf] = (mf * 16 + (lane & 15)) * 128;
#pragma unroll
    for (int q = 0; q < 4; ++q)
        brow[q] = TILE_A + (wn * 64 + q * 16 + (lane & 7) + ((lane & 16) ? 8 : 0)) * 128;
    const int acoladd = (lane & 16) ? 16 : 0;
    const int bcoladd = (lane & 8) ? 16 : 0;
    const int kbase   = kh * 64;         // byte offset of this warp's k-half

    // Prologue
#pragma unroll
    for (int pc = 0; pc < NSTAGE - 1; ++pc) {
        load_chunk(tiles + pc * STAGE_B, Ahi, Whi, m0, n0, pc * BK, tid);
        cpa_commit();
    }

    for (int c = 0; c < NCH; ++c) {
        cpa_wait<NSTAGE - 2>();
        __syncthreads();

        {
            int cn = c + NSTAGE - 1;
            if (cn < NCH) {
                const __nv_bfloat16* As = (cn < 64) ? Ahi : Alo;
                const __nv_bfloat16* Bs = (cn >= 32 && cn < 64) ? Wlo : Whi;
                load_chunk(tiles + (cn & (NSTAGE - 1)) * STAGE_B, As, Bs,
                           m0, n0, (cn & 31) * BK, tid);
            }
            cpa_commit();
        }

        uint32_t st = tiles + (c & (NSTAGE - 1)) * STAGE_B;
#pragma unroll
        for (int kk = 0; kk < 2; ++kk) {           // two k16 in this warp's half
            uint32_t a[4][4], b[4][4];
            int colA = kbase + kk * 32 + acoladd;
            int colB = kbase + kk * 32 + bcoladd;
#pragma unroll
            for (int mf = 0; mf < 4; ++mf)
                ldsm4(a[mf], st + arow[mf] + (uint32_t)(colA ^ xm));
#pragma unroll
            for (int q = 0; q < 4; ++q)
                ldsm4(b[q], st + brow[q] + (uint32_t)(colB ^ xm));
#pragma unroll
            for (int mf = 0; mf < 4; ++mf) {
#pragma unroll
                for (int nf = 0; nf < 8; ++nf) {
                    const uint32_t bp[2] = { b[nf >> 1][(nf & 1) * 2],
                                             b[nf >> 1][(nf & 1) * 2 + 1] };
                    mma16816(acc[mf][nf], a[mf], bp);
                }
            }
        }
    }

    // ---- k-split merge via smem ----
    __syncthreads();   // all LDSM of final chunk done; stage smem reusable
    {
        // each k-group stores the mf-half it will NOT epilogue
        const int mfs = (kh == 0) ? 2 : 0;
#pragma unroll
        for (int mi = 0; mi < 2; ++mi) {
            const int mf = mfs + mi;
#pragma unroll
            for (int nf = 0; nf < 8; ++nf) {
#pragma unroll
                for (int k = 0; k < 4; ++k) {
                    int row = mf * 16 + (lane >> 2) + ((k >= 2) ? 8 : 0);
                    int col = wn * 64 + nf * 8 + (lane & 3) * 2 + (k & 1);
                    gbuf[row * GSTRIDE + col] = acc[mf][nf][k];
                }
            }
        }
    }
    __syncthreads();
    const int mfo = (kh == 0) ? 0 : 2;
#pragma unroll
    for (int mi = 0; mi < 2; ++mi) {
        const int mf = mfo + mi;
#pragma unroll
        for (int nf = 0; nf < 8; ++nf) {
#pragma unroll
            for (int k = 0; k < 4; ++k) {
                int row = mf * 16 + (lane >> 2) + ((k >= 2) ? 8 : 0);
                int col = wn * 64 + nf * 8 + (lane & 3) * 2 + (k & 1);
                acc[mf][nf][k] += gbuf[row * GSTRIDE + col];
            }
        }
    }

    // ---- epilogue: gate exchange + LSTM cell + prediction (each k-group: 2 mf) ----
    const bool oddl = (lane & 1);
    const int slot  = (lane >> 1) & 1;
    const int rloc0 = (lane >> 2) + (oddl ? 8 : 0);

#pragma unroll
    for (int mi = 0; mi < 2; ++mi) {
        const int mf = mfo + mi;
        const int rloc = mf * 16 + rloc0;
        const int m = m0 + rloc;
        const float xin = xvec[(size_t)m * xstride];
        float predp = 0.0f;
#pragma unroll
        for (int nf = 0; nf < 8; ++nf) {
            float c0 = acc[mf][nf][0], c1 = acc[mf][nf][1];
            float c2 = acc[mf][nf][2], c3 = acc[mf][nf][3];
            float t0 = __shfl_xor_sync(0xffffffffu, c0, 1);
            float t1 = __shfl_xor_sync(0xffffffffu, c1, 1);
            float t2 = __shfl_xor_sync(0xffffffffu, c2, 1);
            float t3 = __shfl_xor_sync(0xffffffffu, c3, 1);
            float gi, gf, gg, go;
            if (!oddl) { gi = c0; gf = c1; gg = t0; go = t1; }
            else       { gi = t2; gf = t3; gg = c2; go = c3; }

            const int jl = wn * 16 + nf * 2 + slot;
            const int nb = jl * 4;
            gi += bias_s[nb + 0] + xin * wih_s[nb + 0];
            gf += bias_s[nb + 1] + xin * wih_s[nb + 1];
            gg += bias_s[nb + 2] + xin * wih_s[nb + 2];
            go += bias_s[nb + 3] + xin * wih_s[nb + 3];

            const size_t off = (size_t)m * HID + (j0 + jl);
            float cp = cbuf[off];
            float cn = sig_f(gf) * cp + sig_f(gi) * tanh_f(gg);
            cbuf[off] = cn;
            float hn = sig_f(go) * tanh_f(cn);

            __nv_bfloat16 hi = __float2bfloat16(hn);
            Ahi_n[off] = hi;
            Alo_n[off] = __float2bfloat16(hn - __bfloat162float(hi));
            predp += hn * wlin_s[jl];
        }
        atomicAdd(&rowsum[rloc], predp);
    }
    __syncthreads();
    if (tid < 64)
        atomicAdd(&out[(size_t)(m0 + tid) * TTOT + t], rowsum[tid]);
}

// ---------------- host launch ----------------
extern "C" void kernel_launch(void* const* d_in, const int* in_sizes, int n_in,
                              void* d_out, int out_size) {
    const float* x     = (const float*)d_in[0];
    const float* W_ih  = (const float*)d_in[1];
    const float* W_hh  = (const float*)d_in[2];
    const float* b_ih  = (const float*)d_in[3];
    const float* b_hh  = (const float*)d_in[4];
    const float* W_lin = (const float*)d_in[5];
    const float* b_lin = (const float*)d_in[6];
    float* out = (float*)d_out;

    float *cbuf;
    __nv_bfloat16 *hhi, *hlo, *whi, *wlo;
    cudaGetSymbolAddress((void**)&cbuf, g_c);
    cudaGetSymbolAddress((void**)&hhi,  g_hhi);
    cudaGetSymbolAddress((void**)&hlo,  g_hlo);
    cudaGetSymbolAddress((void**)&whi,  g_whi);
    cudaGetSymbolAddress((void**)&wlo,  g_wlo);

    cudaFuncSetAttribute(lstm_step, cudaFuncAttributeMaxDynamicSharedMemorySize, SMEM_DYN);

    wconv_kernel<<<HID4, 256>>>(W_hh, whi, wlo);
    init_kernel<<<(BH + 255) / 256, 256>>>(cbuf, hhi, hlo, out, b_lin);

    dim3 grid(BATCH / BM, HID4 / BN);

    for (int t = 0; t < TTOT; ++t) {
        const int cur = t & 1;
        const float* xvec;
        int xstride;
        if (t < TOBS) { xvec = x + t;         xstride = TOBS; }
        else          { xvec = out + (t - 1); xstride = TTOT; }

        lstm_step<<<grid, NT, SMEM_DYN>>>(
            hhi + (size_t)cur * BH, hlo + (size_t)cur * BH,
            hhi + (size_t)(1 - cur) * BH, hlo + (size_t)(1 - cur) * BH,
            cbuf, whi, wlo,
            W_ih, b_ih, b_hh, W_lin,
            out, xvec, xstride, t);
    }
}

// round 9
// speedup vs baseline: 5.0087x; 5.0087x over previous
#include <cuda_runtime.h>
#include <cuda_bf16.h>
#include <cstdint>

#define BATCH 256
#define TOBS  80
#define TTOT  160
#define HID   2048
#define HID4  8192
#define BH    (BATCH * HID)

#define NT      256                  // 8 warps: wn in 0..3 (n) x kh in 0..1 (k-half)
#define BM      64
#define BN      128
#define BK      64                   // K per chunk (bf16) = 128 bytes/row
#define NCH     96                   // 3 * (2048/64) concatenated-K chunks
#define NSTAGE  4
#define TILE_A  (BM * 128)           // 8 KB
#define TILE_BB (BN * 128)           // 16 KB
#define STAGE_B (TILE_A + TILE_BB)   // 24 KB
#define CTRL_B  2048
#define SMEM_DYN (1024 + CTRL_B + NSTAGE * STAGE_B)
#define GSTRIDE 132                  // gates smem row stride (floats)

// ---------------- persistent device state ----------------
__device__ float          g_c[BH];
__device__ __nv_bfloat16  g_hhi[2 * BH];
__device__ __nv_bfloat16  g_hlo[2 * BH];
__device__ __nv_bfloat16  g_whi[(size_t)HID4 * HID];   // gate-interleaved W_hh hi
__device__ __nv_bfloat16  g_wlo[(size_t)HID4 * HID];   // gate-interleaved W_hh lo

// ---------------- helpers ----------------
static __device__ __forceinline__ uint32_t smem_u32(const void* p) {
    uint32_t a;
    asm("{ .reg .u64 t; cvta.to.shared.u64 t, %1; cvt.u32.u64 %0, t; }" : "=r"(a) : "l"(p));
    return a;
}
static __device__ __forceinline__ void cpa16(uint32_t dst, const void* src) {
    asm volatile("cp.async.cg.shared.global [%0], [%1], 16;" :: "r"(dst), "l"(src) : "memory");
}
static __device__ __forceinline__ void cpa_commit() {
    asm volatile("cp.async.commit_group;" ::: "memory");
}
template <int N>
static __device__ __forceinline__ void cpa_wait() {
    asm volatile("cp.async.wait_group %0;" :: "n"(N) : "memory");
}
static __device__ __forceinline__ void ldsm4(uint32_t* r, uint32_t a) {
    asm volatile("ldmatrix.sync.aligned.m8n8.x4.shared.b16 {%0,%1,%2,%3}, [%4];"
                 : "=r"(r[0]), "=r"(r[1]), "=r"(r[2]), "=r"(r[3]) : "r"(a));
}
static __device__ __forceinline__ void mma16816(float* d, const uint32_t* a, const uint32_t* b) {
    asm volatile("mma.sync.aligned.m16n8k16.row.col.f32.bf16.bf16.f32 "
                 "{%0,%1,%2,%3}, {%4,%5,%6,%7}, {%8,%9}, {%0,%1,%2,%3};"
                 : "+f"(d[0]), "+f"(d[1]), "+f"(d[2]), "+f"(d[3])
                 : "r"(a[0]), "r"(a[1]), "r"(a[2]), "r"(a[3]), "r"(b[0]), "r"(b[1]));
}
static __device__ __forceinline__ float sig_f(float x) {
    return __fdividef(1.0f, 1.0f + __expf(-x));
}
static __device__ __forceinline__ float tanh_f(float x) {
    return __fdividef(2.0f, 1.0f + __expf(-2.0f * x)) - 1.0f;
}

// Load one chunk (A tile BMxBK + B tile BNxBK) into a stage via cp.async, SW128.
static __device__ __forceinline__ void load_chunk(
    uint32_t st, const __nv_bfloat16* __restrict__ A, const __nv_bfloat16* __restrict__ B,
    int m0, int n0, int koff, int tid)
{
    // A: 64 rows * 8 16B-chunks = 512 units, 256 threads -> 2 iters
#pragma unroll
    for (int r = 0; r < 2; ++r) {
        int q   = tid + NT * r;
        int row = q >> 3;
        int cb  = (q & 7) * 16;
        uint32_t sw = (uint32_t)(row * 128) + (uint32_t)(cb ^ ((row & 7) * 16));
        const char* ga = (const char*)(A + (size_t)(m0 + row) * HID + koff) + cb;
        cpa16(st + sw, ga);
    }
    // B: 128 rows * 8 = 1024 units -> 4 iters
#pragma unroll
    for (int r = 0; r < 4; ++r) {
        int q   = tid + NT * r;
        int row = q >> 3;
        int cb  = (q & 7) * 16;
        uint32_t sw = (uint32_t)(row * 128) + (uint32_t)(cb ^ ((row & 7) * 16));
        const char* gb = (const char*)(B + (size_t)(n0 + row) * HID + koff) + cb;
        cpa16(st + TILE_A + sw, gb);
    }
}

// ---------------- prep kernels ----------------
__global__ void wconv_kernel(const float* __restrict__ W,
                             __nv_bfloat16* __restrict__ whi,
                             __nv_bfloat16* __restrict__ wlo)
{
    int n = blockIdx.x;                  // gate-interleaved row: n = 4*j + g
    int j = n >> 2, g = n & 3;
    const float4* src = (const float4*)(W + ((size_t)g * HID + j) * HID);
    size_t dst = (size_t)n * HID;
#pragma unroll
    for (int r = 0; r < 2; ++r) {
        int q = threadIdx.x + 256 * r;
        float4 v = src[q];
        int k = q * 4;
        float xs[4] = {v.x, v.y, v.z, v.w};
#pragma unroll
        for (int c = 0; c < 4; ++c) {
            __nv_bfloat16 hi = __float2bfloat16(xs[c]);
            whi[dst + k + c] = hi;
            wlo[dst + k + c] = __float2bfloat16(xs[c] - __bfloat162float(hi));
        }
    }
}

__global__ void init_kernel(float* __restrict__ cbuf,
                            __nv_bfloat16* __restrict__ h0hi,
                            __nv_bfloat16* __restrict__ h0lo,
                            float* __restrict__ out,
                            const float* __restrict__ b_lin)
{
    int i = blockIdx.x * blockDim.x + threadIdx.x;
    if (i < BH) {
        cbuf[i] = 0.0f;
        h0hi[i] = __float2bfloat16(0.0f);
        h0lo[i] = __float2bfloat16(0.0f);
    }
    if (i < BATCH * TTOT) out[i] = b_lin[0];
}

// ---------------- fused LSTM step ----------------
__global__ void __launch_bounds__(NT, 2)
lstm_step(const __nv_bfloat16* __restrict__ Ahi, const __nv_bfloat16* __restrict__ Alo,
          __nv_bfloat16* __restrict__ Ahi_n, __nv_bfloat16* __restrict__ Alo_n,
          float* __restrict__ cbuf,
          const __nv_bfloat16* __restrict__ Whi, const __nv_bfloat16* __restrict__ Wlo,
          const float* __restrict__ W_ih, const float* __restrict__ b_ih,
          const float* __restrict__ b_hh, const float* __restrict__ W_lin,
          float* __restrict__ out,
          const float* __restrict__ xvec, int xstride, int t)
{
    extern __shared__ char smem_raw[];
    const int tid  = threadIdx.x;
    const int wid  = tid >> 5;
    const int lane = tid & 31;
    const int wn   = wid & 3;            // n-warp: cols wn*32..wn*32+31
    const int kh   = wid >> 2;           // k-half: bytes kh*64.. of each 128B row
    const int m0 = blockIdx.x * BM;
    const int n0 = blockIdx.y * BN;      // gate-interleaved col base
    const int j0 = n0 >> 2;

    uint32_t sb    = smem_u32(smem_raw);
    uint32_t sbase = (sb + 1023) & ~1023u;
    char*    ctrl  = smem_raw + (sbase - sb);
    uint32_t tiles = sbase + CTRL_B;
    float* bias_s = (float*)(ctrl + 0);      // 128
    float* wih_s  = (float*)(ctrl + 512);    // 128
    float* rowsum = (float*)(ctrl + 1024);   // 64
    float* wlin_s = (float*)(ctrl + 1536);   // 32
    float* gbuf   = (float*)(smem_raw + (tiles - sb));  // 64*GSTRIDE floats (reuses stages)

    if (tid < 128) {                         // GUARD restored (R7 bug: smem aliasing without it)
        int j = j0 + (tid >> 2);
        int g = tid & 3;
        bias_s[tid] = b_ih[g * HID + j] + b_hh[g * HID + j];
        wih_s[tid]  = W_ih[g * HID + j];
    }
    if (tid < 64) rowsum[tid] = 0.0f;
    if (tid < 32) wlin_s[tid] = W_lin[j0 + tid];
    __syncthreads();

    float acc[4][4][4];                  // mf(4 x m16) x nf(4 x n8) x 4
#pragma unroll
    for (int i = 0; i < 4; ++i)
#pragma unroll
        for (int jf = 0; jf < 4; ++jf)
#pragma unroll
            for (int kf = 0; kf < 4; ++kf) acc[i][jf][kf] = 0.0f;

    // ldmatrix addressing (SW128: xor (row&7)*16; row-invariant per lane)
    const int xm = (lane & 7) * 16;
    int arow[4], brow[2];
#pragma unroll
    for (int mf = 0; mf < 4; ++mf)
        arow[mf] = (mf * 16 + (lane & 15)) * 128;
#pragma unroll
    for (int q = 0; q < 2; ++q)
        brow[q] = TILE_A + (wn * 32 + q * 16 + (lane & 7) + ((lane & 16) ? 8 : 0)) * 128;
    const int acoladd = (lane & 16) ? 16 : 0;
    const int bcoladd = (lane & 8) ? 16 : 0;
    const int kbase   = kh * 64;         // byte offset of this warp's k-half

    // Prologue
#pragma unroll
    for (int pc = 0; pc < NSTAGE - 1; ++pc) {
        load_chunk(tiles + pc * STAGE_B, Ahi, Whi, m0, n0, pc * BK, tid);
        cpa_commit();
    }

    for (int c = 0; c < NCH; ++c) {
        cpa_wait<NSTAGE - 2>();
        __syncthreads();

        {
            int cn = c + NSTAGE - 1;
            if (cn < NCH) {
                const __nv_bfloat16* As = (cn < 64) ? Ahi : Alo;
                const __nv_bfloat16* Bs = (cn >= 32 && cn < 64) ? Wlo : Whi;
                load_chunk(tiles + (cn & (NSTAGE - 1)) * STAGE_B, As, Bs,
                           m0, n0, (cn & 31) * BK, tid);
            }
            cpa_commit();
        }

        uint32_t st = tiles + (c & (NSTAGE - 1)) * STAGE_B;
#pragma unroll
        for (int kk = 0; kk < 2; ++kk) {           // two k16 within this warp's k-half
            uint32_t a[4][4], b[2][4];
            int colA = kbase + kk * 32 + acoladd;
            int colB = kbase + kk * 32 + bcoladd;
#pragma unroll
            for (int mf = 0; mf < 4; ++mf)
                ldsm4(a[mf], st + arow[mf] + (uint32_t)(colA ^ xm));
#pragma unroll
            for (int q = 0; q < 2; ++q)
                ldsm4(b[q], st + brow[q] + (uint32_t)(colB ^ xm));
#pragma unroll
            for (int mf = 0; mf < 4; ++mf) {
#pragma unroll
                for (int nf = 0; nf < 4; ++nf) {
                    const uint32_t bp[2] = { b[nf >> 1][(nf & 1) * 2],
                                             b[nf >> 1][(nf & 1) * 2 + 1] };
                    mma16816(acc[mf][nf], a[mf], bp);
                }
            }
        }
    }

    // ---- k-split merge via smem (gbuf reuses stage memory) ----
    __syncthreads();   // all LDSM of final chunk done; stage smem reusable
    {
        const int mfs = (kh == 0) ? 2 : 0;   // store the half we will NOT epilogue
#pragma unroll
        for (int mi = 0; mi < 2; ++mi) {
            const int mf = mfs + mi;
#pragma unroll
            for (int nf = 0; nf < 4; ++nf) {
#pragma unroll
                for (int k = 0; k < 4; ++k) {
                    int row = mf * 16 + (lane >> 2) + ((k >= 2) ? 8 : 0);
                    int col = wn * 32 + nf * 8 + (lane & 3) * 2 + (k & 1);
                    gbuf[row * GSTRIDE + col] = acc[mf][nf][k];
                }
            }
        }
    }
    __syncthreads();
    const int mfo = (kh == 0) ? 0 : 2;       // the half we DO epilogue
#pragma unroll
    for (int mi = 0; mi < 2; ++mi) {
        const int mf = mfo + mi;
#pragma unroll
        for (int nf = 0; nf < 4; ++nf) {
#pragma unroll
            for (int k = 0; k < 4; ++k) {
                int row = mf * 16 + (lane >> 2) + ((k >= 2) ? 8 : 0);
                int col = wn * 32 + nf * 8 + (lane & 3) * 2 + (k & 1);
                acc[mf][nf][k] += gbuf[row * GSTRIDE + col];
            }
        }
    }

    // ---- epilogue: gate exchange + LSTM cell + prediction (each k-group: 2 mf) ----
    const bool oddl = (lane & 1);
    const int slot  = (lane >> 1) & 1;
    const int rloc0 = (lane >> 2) + (oddl ? 8 : 0);

#pragma unroll
    for (int mi = 0; mi < 2; ++mi) {
        const int mf = mfo + mi;
        const int rloc = mf * 16 + rloc0;
        const int m = m0 + rloc;
        const float xin = xvec[(size_t)m * xstride];
        float predp = 0.0f;
#pragma unroll
        for (int nf = 0; nf < 4; ++nf) {
            float c0 = acc[mf][nf][0], c1 = acc[mf][nf][1];
            float c2 = acc[mf][nf][2], c3 = acc[mf][nf][3];
            float t0 = __shfl_xor_sync(0xffffffffu, c0, 1);
            float t1 = __shfl_xor_sync(0xffffffffu, c1, 1);
            float t2 = __shfl_xor_sync(0xffffffffu, c2, 1);
            float t3 = __shfl_xor_sync(0xffffffffu, c3, 1);
            float gi, gf, gg, go;
            if (!oddl) { gi = c0; gf = c1; gg = t0; go = t1; }
            else       { gi = t2; gf = t3; gg = c2; go = c3; }

            const int jl = wn * 8 + nf * 2 + slot;
            const int nb = jl * 4;
            gi += bias_s[nb + 0] + xin * wih_s[nb + 0];
            gf += bias_s[nb + 1] + xin * wih_s[nb + 1];
            gg += bias_s[nb + 2] + xin * wih_s[nb + 2];
            go += bias_s[nb + 3] + xin * wih_s[nb + 3];

            const size_t off = (size_t)m * HID + (j0 + jl);
            float cp = cbuf[off];
            float cn = sig_f(gf) * cp + sig_f(gi) * tanh_f(gg);
            cbuf[off] = cn;
            float hn = sig_f(go) * tanh_f(cn);

            __nv_bfloat16 hi = __float2bfloat16(hn);
            Ahi_n[off] = hi;
            Alo_n[off] = __float2bfloat16(hn - __bfloat162float(hi));
            predp += hn * wlin_s[jl];
        }
        atomicAdd(&rowsum[rloc], predp);
    }
    __syncthreads();
    if (tid < 64)
        atomicAdd(&out[(size_t)(m0 + tid) * TTOT + t], rowsum[tid]);
}

// ---------------- host launch ----------------
extern "C" void kernel_launch(void* const* d_in, const int* in_sizes, int n_in,
                              void* d_out, int out_size) {
    const float* x     = (const float*)d_in[0];
    const float* W_ih  = (const float*)d_in[1];
    const float* W_hh  = (const float*)d_in[2];
    const float* b_ih  = (const float*)d_in[3];
    const float* b_hh  = (const float*)d_in[4];
    const float* W_lin = (const float*)d_in[5];
    const float* b_lin = (const float*)d_in[6];
    float* out = (float*)d_out;

    float *cbuf;
    __nv_bfloat16 *hhi, *hlo, *whi, *wlo;
    cudaGetSymbolAddress((void**)&cbuf, g_c);
    cudaGetSymbolAddress((void**)&hhi,  g_hhi);
    cudaGetSymbolAddress((void**)&hlo,  g_hlo);
    cudaGetSymbolAddress((void**)&whi,  g_whi);
    cudaGetSymbolAddress((void**)&wlo,  g_wlo);

    cudaFuncSetAttribute(lstm_step, cudaFuncAttributeMaxDynamicSharedMemorySize, SMEM_DYN);

    wconv_kernel<<<HID4, 256>>>(W_hh, whi, wlo);
    init_kernel<<<(BH + 255) / 256, 256>>>(cbuf, hhi, hlo, out, b_lin);

    dim3 grid(BATCH / BM, HID4 / BN);

    for (int t = 0; t < TTOT; ++t) {
        const int cur = t & 1;
        const float* xvec;
        int xstride;
        if (t < TOBS) { xvec = x + t;         xstride = TOBS; }
        else          { xvec = out + (t - 1); xstride = TTOT; }

        lstm_step<<<grid, NT, SMEM_DYN>>>(
            hhi + (size_t)cur * BH, hlo + (size_t)cur * BH,
            hhi + (size_t)(1 - cur) * BH, hlo + (size_t)(1 - cur) * BH,
            cbuf, whi, wlo,
            W_ih, b_ih, b_hh, W_lin,
            out, xvec, xstride, t);
    }
}